// round 1
// baseline (speedup 1.0000x reference)
#include <cuda_runtime.h>
#include <math.h>

#define B 32
#define T 2048
#define H 1024
#define NEGV (-1e9f)

// Scratch (no allocs allowed in kernel_launch)
__device__ float g_dec_p[B * H];
__device__ float g_scores[B * T];

// ---------------------------------------------------------------------------
// Kernel A: dec_p[b][o] = dot(dec[b,:], W_dec[o,:])   (one warp per output)
// ---------------------------------------------------------------------------
__global__ void dec_proj_kernel(const float* __restrict__ dec,
                                const float* __restrict__ Wd) {
    int warp = (blockIdx.x * blockDim.x + threadIdx.x) >> 5;
    int lane = threadIdx.x & 31;
    if (warp >= B * H) return;
    int b = warp >> 10;       // / H
    int o = warp & (H - 1);
    const float* dptr = dec + (size_t)b * H;
    const float* wptr = Wd + (size_t)o * H;
    float acc = 0.f;
#pragma unroll 8
    for (int h = lane; h < H; h += 32) acc += dptr[h] * wptr[h];
#pragma unroll
    for (int off = 16; off; off >>= 1)
        acc += __shfl_xor_sync(0xffffffffu, acc, off);
    if (lane == 0) g_dec_p[warp] = acc;
}

// ---------------------------------------------------------------------------
// Kernel B: fused scores GEMM
//   scores[b,t] = sum_n v[n] * tanh( dot(enc[b,t,:], W_enc[n,:]) + dec_p[b,n] )
// Block tile 64(m) x 64(n), BK=16, 4x4 micro-tile, 256 threads.
// Each block owns 64 m-rows (all within one b since 2048 % 64 == 0) and loops
// over ALL n -> no inter-block reduction needed.
// ---------------------------------------------------------------------------
#define BM 64
#define BN 64
#define BK 16

__global__ __launch_bounds__(256, 2) void scores_kernel(
    const float* __restrict__ enc, const float* __restrict__ We,
    const float* __restrict__ v) {
    __shared__ float As[BM][BK + 1];
    __shared__ float Bs[BN][BK + 1];
    __shared__ float srow[BM];

    const int tid = threadIdx.x;
    const int tx = tid & 15;        // n-group 0..15
    const int ty = tid >> 4;        // m-group 0..15
    const int m0 = blockIdx.x * BM;
    const int b  = m0 >> 11;        // / T
    const int t0 = m0 & (T - 1);

    const float* X = enc + (size_t)m0 * H;

    // per-thread loader coords: one float4 each (64*16 floats / 256 threads)
    const int lrow = tid >> 2;
    const int lc4  = (tid & 3) * 4;

    float s[4] = {0.f, 0.f, 0.f, 0.f};

    for (int n0 = 0; n0 < H; n0 += BN) {
        float c[4][4];
#pragma unroll
        for (int i = 0; i < 4; i++)
#pragma unroll
            for (int j = 0; j < 4; j++) c[i][j] = 0.f;

        for (int k0 = 0; k0 < H; k0 += BK) {
            float4 xa = *(const float4*)(X + (size_t)lrow * H + k0 + lc4);
            As[lrow][lc4 + 0] = xa.x;
            As[lrow][lc4 + 1] = xa.y;
            As[lrow][lc4 + 2] = xa.z;
            As[lrow][lc4 + 3] = xa.w;
            float4 wb = *(const float4*)(We + (size_t)(n0 + lrow) * H + k0 + lc4);
            Bs[lrow][lc4 + 0] = wb.x;
            Bs[lrow][lc4 + 1] = wb.y;
            Bs[lrow][lc4 + 2] = wb.z;
            Bs[lrow][lc4 + 3] = wb.w;
            __syncthreads();

#pragma unroll
            for (int kk = 0; kk < BK; kk++) {
                float a[4], bb[4];
#pragma unroll
                for (int i = 0; i < 4; i++) a[i] = As[ty * 4 + i][kk];
#pragma unroll
                for (int j = 0; j < 4; j++) bb[j] = Bs[tx * 4 + j][kk];
#pragma unroll
                for (int i = 0; i < 4; i++)
#pragma unroll
                    for (int j = 0; j < 4; j++) c[i][j] += a[i] * bb[j];
            }
            __syncthreads();
        }

        // fused epilogue: tanh(+dec_p) then weighted reduce over n
#pragma unroll
        for (int j = 0; j < 4; j++) {
            int n = n0 + tx * 4 + j;
            float dv = g_dec_p[b * H + n];
            float vv = v[n];
#pragma unroll
            for (int i = 0; i < 4; i++)
                s[i] += tanhf(c[i][j] + dv) * vv;
        }
    }

    // reduce per-row partials across the 16 n-groups
    if (tid < BM) srow[tid] = 0.f;
    __syncthreads();
#pragma unroll
    for (int i = 0; i < 4; i++) atomicAdd(&srow[ty * 4 + i], s[i]);
    __syncthreads();
    if (tid < BM) g_scores[b * T + t0 + tid] = srow[tid];
}

// ---------------------------------------------------------------------------
// Kernel C: masked softmax over T, one block per batch row
// ---------------------------------------------------------------------------
__global__ void softmax_kernel(const int* __restrict__ mask,
                               float* __restrict__ attn) {
    const int b = blockIdx.x;
    const int tid = threadIdx.x;
    __shared__ float red[8];

    float vals[8];
    float mx = -INFINITY;
#pragma unroll
    for (int i = 0; i < 8; i++) {
        int t = tid + i * 256;
        float sc = g_scores[b * T + t];
        if (mask[b * T + t] == 0) sc = NEGV;
        vals[i] = sc;
        mx = fmaxf(mx, sc);
    }
#pragma unroll
    for (int off = 16; off; off >>= 1)
        mx = fmaxf(mx, __shfl_xor_sync(0xffffffffu, mx, off));
    if ((tid & 31) == 0) red[tid >> 5] = mx;
    __syncthreads();
    if (tid < 32) {
        float m = (tid < 8) ? red[tid] : -INFINITY;
#pragma unroll
        for (int off = 4; off; off >>= 1)
            m = fmaxf(m, __shfl_xor_sync(0xffffffffu, m, off));
        if (tid == 0) red[0] = m;
    }
    __syncthreads();
    mx = red[0];

    float sum = 0.f;
#pragma unroll
    for (int i = 0; i < 8; i++) {
        vals[i] = expf(vals[i] - mx);
        sum += vals[i];
    }
#pragma unroll
    for (int off = 16; off; off >>= 1)
        sum += __shfl_xor_sync(0xffffffffu, sum, off);
    __syncthreads();
    if ((tid & 31) == 0) red[tid >> 5] = sum;
    __syncthreads();
    if (tid < 32) {
        float ssum = (tid < 8) ? red[tid] : 0.f;
#pragma unroll
        for (int off = 4; off; off >>= 1)
            ssum += __shfl_xor_sync(0xffffffffu, ssum, off);
        if (tid == 0) red[0] = ssum;
    }
    __syncthreads();
    const float inv = 1.f / red[0];
#pragma unroll
    for (int i = 0; i < 8; i++)
        attn[b * T + tid + i * 256] = vals[i] * inv;
}

// ---------------------------------------------------------------------------
// Kernel D: context[b,h] = sum_t attn[b,t] * enc[b,t,h]
// grid (H/256, B), weights cached in smem, coalesced along h
// ---------------------------------------------------------------------------
__global__ void context_kernel(const float* __restrict__ enc,
                               const float* __restrict__ attn,
                               float* __restrict__ ctx) {
    __shared__ float w[T];
    const int b = blockIdx.y;
    const int tid = threadIdx.x;
    for (int t = tid; t < T; t += 256) w[t] = attn[b * T + t];
    __syncthreads();

    const int h = blockIdx.x * 256 + tid;
    const float* e = enc + (size_t)b * T * H + h;
    float acc0 = 0.f, acc1 = 0.f, acc2 = 0.f, acc3 = 0.f;
#pragma unroll 4
    for (int t = 0; t < T; t += 4) {
        acc0 += w[t + 0] * e[(size_t)(t + 0) * H];
        acc1 += w[t + 1] * e[(size_t)(t + 1) * H];
        acc2 += w[t + 2] * e[(size_t)(t + 2) * H];
        acc3 += w[t + 3] * e[(size_t)(t + 3) * H];
    }
    ctx[b * H + h] = (acc0 + acc1) + (acc2 + acc3);
}

// ---------------------------------------------------------------------------
extern "C" void kernel_launch(void* const* d_in, const int* in_sizes, int n_in,
                              void* d_out, int out_size) {
    const float* dec  = (const float*)d_in[0];  // [B,H]
    const float* enc  = (const float*)d_in[1];  // [B,T,H]
    const int*   mask = (const int*)d_in[2];    // [B,T]
    const float* We   = (const float*)d_in[3];  // [H,H]
    const float* Wd   = (const float*)d_in[4];  // [H,H]
    const float* v    = (const float*)d_in[5];  // [H]

    float* ctx  = (float*)d_out;                // [B,H]
    float* attn = (float*)d_out + B * H;        // [B,T]

    dec_proj_kernel<<<(B * H * 32 + 255) / 256, 256>>>(dec, Wd);
    scores_kernel<<<(B * T) / BM, 256>>>(enc, We, v);
    softmax_kernel<<<B, 256>>>(mask, attn);
    context_kernel<<<dim3(H / 256, B), 256>>>(enc, attn, ctx);
}

// round 4
// speedup vs baseline: 3.5059x; 3.5059x over previous
#include <cuda_runtime.h>
#include <cuda_bf16.h>
#include <cstdint>
#include <math.h>

#define B 32
#define T 2048
#define H 1024
#define NEGV (-1e9f)

// ---------------------------------------------------------------------------
// Device scratch
// ---------------------------------------------------------------------------
__device__ __align__(256) __nv_bfloat16 g_enc_hi[B * T * H];
__device__ __align__(256) __nv_bfloat16 g_enc_lo[B * T * H];
__device__ __align__(256) __nv_bfloat16 g_We_hi[H * H];
__device__ __align__(256) __nv_bfloat16 g_We_lo[H * H];
__device__ float g_dec_p[B * H];
__device__ float g_scores[B * T];

// ---------------------------------------------------------------------------
// helpers
// ---------------------------------------------------------------------------
__device__ __forceinline__ uint32_t smem_u32(const void* p) {
    uint32_t a;
    asm("{ .reg .u64 t; cvta.to.shared.u64 t, %1; cvt.u32.u64 %0, t; }" : "=r"(a) : "l"(p));
    return a;
}
#define CP_ASYNC_16(dst, src) \
    asm volatile("cp.async.cg.shared.global [%0], [%1], 16;" :: "r"(dst), "l"(src) : "memory")
#define CP_COMMIT() asm volatile("cp.async.commit_group;" ::: "memory")
#define CP_WAIT2()  asm volatile("cp.async.wait_group 2;" ::: "memory")

#define LDSM_X4(r0, r1, r2, r3, addr) \
    asm volatile("ldmatrix.sync.aligned.m8n8.x4.shared.b16 {%0,%1,%2,%3}, [%4];" \
        : "=r"(r0), "=r"(r1), "=r"(r2), "=r"(r3) : "r"(addr))

#define MMA16816(c0, c1, c2, c3, a0, a1, a2, a3, b0, b1) \
    asm volatile("mma.sync.aligned.m16n8k16.row.col.f32.bf16.bf16.f32 " \
        "{%0,%1,%2,%3}, {%4,%5,%6,%7}, {%8,%9}, {%0,%1,%2,%3};" \
        : "+f"(c0), "+f"(c1), "+f"(c2), "+f"(c3) \
        : "r"(a0), "r"(a1), "r"(a2), "r"(a3), "r"(b0), "r"(b1))

// fast tanh: 2 MUFU + FMAs, abs err ~1e-6
__device__ __forceinline__ float fast_tanh(float x) {
    float e;
    asm("ex2.approx.f32 %0, %1;" : "=f"(e) : "f"(x * 2.8853900817779268f));
    float r;
    asm("rcp.approx.f32 %0, %1;" : "=f"(r) : "f"(e + 1.0f));
    return fmaf(-2.0f, r, 1.0f);
}

// ---------------------------------------------------------------------------
// Split kernels: fp32 -> (hi, lo) bf16
// ---------------------------------------------------------------------------
__global__ void split_enc_kernel(const float* __restrict__ src) {
    int i = (blockIdx.x * blockDim.x + threadIdx.x) * 4;
    if (i >= B * T * H) return;
    float4 x = *(const float4*)(src + i);
    __nv_bfloat16 h0 = __float2bfloat16(x.x), h1 = __float2bfloat16(x.y);
    __nv_bfloat16 h2 = __float2bfloat16(x.z), h3 = __float2bfloat16(x.w);
    __nv_bfloat16 l0 = __float2bfloat16(x.x - __bfloat162float(h0));
    __nv_bfloat16 l1 = __float2bfloat16(x.y - __bfloat162float(h1));
    __nv_bfloat16 l2 = __float2bfloat16(x.z - __bfloat162float(h2));
    __nv_bfloat16 l3 = __float2bfloat16(x.w - __bfloat162float(h3));
    __nv_bfloat162 p;
    p.x = h0; p.y = h1; *(__nv_bfloat162*)(g_enc_hi + i) = p;
    p.x = h2; p.y = h3; *(__nv_bfloat162*)(g_enc_hi + i + 2) = p;
    p.x = l0; p.y = l1; *(__nv_bfloat162*)(g_enc_lo + i) = p;
    p.x = l2; p.y = l3; *(__nv_bfloat162*)(g_enc_lo + i + 2) = p;
}

__global__ void split_We_kernel(const float* __restrict__ src) {
    int i = (blockIdx.x * blockDim.x + threadIdx.x) * 4;
    if (i >= H * H) return;
    float4 x = *(const float4*)(src + i);
    __nv_bfloat16 h0 = __float2bfloat16(x.x), h1 = __float2bfloat16(x.y);
    __nv_bfloat16 h2 = __float2bfloat16(x.z), h3 = __float2bfloat16(x.w);
    __nv_bfloat16 l0 = __float2bfloat16(x.x - __bfloat162float(h0));
    __nv_bfloat16 l1 = __float2bfloat16(x.y - __bfloat162float(h1));
    __nv_bfloat16 l2 = __float2bfloat16(x.z - __bfloat162float(h2));
    __nv_bfloat16 l3 = __float2bfloat16(x.w - __bfloat162float(h3));
    __nv_bfloat162 p;
    p.x = h0; p.y = h1; *(__nv_bfloat162*)(g_We_hi + i) = p;
    p.x = h2; p.y = h3; *(__nv_bfloat162*)(g_We_hi + i + 2) = p;
    p.x = l0; p.y = l1; *(__nv_bfloat162*)(g_We_lo + i) = p;
    p.x = l2; p.y = l3; *(__nv_bfloat162*)(g_We_lo + i + 2) = p;
}

// ---------------------------------------------------------------------------
// dec_p[b][o] = dot(dec[b,:], W_dec[o,:])
// ---------------------------------------------------------------------------
__global__ void dec_proj_kernel(const float* __restrict__ dec,
                                const float* __restrict__ Wd) {
    int warp = (blockIdx.x * blockDim.x + threadIdx.x) >> 5;
    int lane = threadIdx.x & 31;
    if (warp >= B * H) return;
    int b = warp >> 10;
    int o = warp & (H - 1);
    const float* dptr = dec + (size_t)b * H;
    const float* wptr = Wd + (size_t)o * H;
    float acc = 0.f;
#pragma unroll 8
    for (int h = lane; h < H; h += 32) acc += dptr[h] * wptr[h];
#pragma unroll
    for (int off = 16; off; off >>= 1) acc += __shfl_xor_sync(0xffffffffu, acc, off);
    if (lane == 0) g_dec_p[warp] = acc;
}

// ---------------------------------------------------------------------------
// Fused HMMA scores kernel
//   Block tile 128(M) x 256(N), K' = 3072 (bf16x3), k-tile 64, 4-stage cp.async
//   8 warps (2x4), warp tile 64x64 via m16n8k16 bf16 mma.sync
// ---------------------------------------------------------------------------
#define NJOBS 192          // 4 n-chunks * 48 k-tiles
#define A_STAGE 16384      // 128 x 64 bf16
#define B_STAGE 32768      // 256 x 64 bf16
#define B_OFF   65536      // 4 A stages
#define VDP_OFF 196608     // 4 B stages end
#define SROW_OFF 204800
#define SMEM_TOTAL 205824

__device__ __forceinline__ void load_job(uint32_t sb, int slot, int j, int m0) {
    const int c = j / 48, kt = j - c * 48;
    const int region = kt >> 4;           // 0: hi*hi, 1: hi*lo, 2: lo*hi
    const int ksrc = (kt & 15) << 6;
    const __nv_bfloat16* Asrc = (region == 2) ? g_enc_lo : g_enc_hi;
    const __nv_bfloat16* Bsrc = (region == 1) ? g_We_lo : g_We_hi;
    const uint32_t aB = sb + slot * A_STAGE;
    const uint32_t bB = sb + B_OFF + slot * B_STAGE;
    const int tid = threadIdx.x;
    const int n0 = c << 8;
#pragma unroll
    for (int i = 0; i < 4; i++) {         // A: 128 rows x 128B
        int ch = i * 256 + tid;
        int row = ch >> 3, cu = ch & 7;
        uint32_t dst = aB + row * 128 + ((cu ^ (row & 7)) << 4);
        CP_ASYNC_16(dst, Asrc + (size_t)(m0 + row) * H + ksrc + cu * 8);
    }
#pragma unroll
    for (int i = 0; i < 8; i++) {         // B: 256 rows x 128B
        int ch = i * 256 + tid;
        int row = ch >> 3, cu = ch & 7;
        uint32_t dst = bB + row * 128 + ((cu ^ (row & 7)) << 4);
        CP_ASYNC_16(dst, Bsrc + (size_t)(n0 + row) * H + ksrc + cu * 8);
    }
}

__global__ __launch_bounds__(256, 1) void scores_tc_kernel(const float* __restrict__ v_g) {
    extern __shared__ char sm[];
    const uint32_t sb = smem_u32(sm);
    const int tid = threadIdx.x;
    const int wid = tid >> 5, lane = tid & 31;
    const int wm = wid >> 2, wn = wid & 3;
    const int m0 = blockIdx.x * 128;
    const int b = m0 >> 11;

    float2* vdp = (float2*)(sm + VDP_OFF);
    float* srow = (float*)(sm + SROW_OFF);
    for (int n = tid; n < H; n += 256) {
        float2 t;
        t.x = g_dec_p[b * H + n];
        t.y = v_g[n];
        vdp[n] = t;
    }
    if (tid < 128) srow[tid] = 0.f;

    // ldmatrix per-lane geometry
    int rA128[4], rAx[4], rB128[4], rBx[4];
#pragma unroll
    for (int mt = 0; mt < 4; mt++) {
        int row = wm * 64 + mt * 16 + ((lane >> 3) & 1) * 8 + (lane & 7);
        rA128[mt] = row * 128;
        rAx[mt] = row & 7;
    }
#pragma unroll
    for (int np = 0; np < 4; np++) {
        int row = wn * 64 + np * 16 + ((lane >> 4) << 3) + (lane & 7);
        rB128[np] = row * 128;
        rBx[np] = row & 7;
    }
    const int aU = lane >> 4;
    const int bU = (lane >> 3) & 1;

    __syncthreads();

    load_job(sb, 0, 0, m0); CP_COMMIT();
    load_job(sb, 1, 1, m0); CP_COMMIT();
    load_job(sb, 2, 2, m0); CP_COMMIT();

    float c[4][8][4];
    float accA[4] = {0.f, 0.f, 0.f, 0.f};
    float accB[4] = {0.f, 0.f, 0.f, 0.f};
    int cch = 0, kt = 0;

#pragma unroll 1
    for (int j = 0; j < NJOBS; j++) {
        CP_WAIT2();
        __syncthreads();
        {
            const int jn = j + 3;
            if (jn < NJOBS) load_job(sb, jn & 3, jn, m0);
            CP_COMMIT();
        }

        if (kt == 0) {
#pragma unroll
            for (int mt = 0; mt < 4; mt++)
#pragma unroll
                for (int nt = 0; nt < 8; nt++)
#pragma unroll
                    for (int q = 0; q < 4; q++) c[mt][nt][q] = 0.f;
        }

        const int slot = j & 3;
        const uint32_t aBase = sb + slot * A_STAGE;
        const uint32_t bBase = sb + B_OFF + slot * B_STAGE;

#pragma unroll
        for (int ks = 0; ks < 4; ks++) {
            uint32_t a[4][4];
#pragma unroll
            for (int mt = 0; mt < 4; mt++) {
                uint32_t ad = aBase + rA128[mt] + ((((ks << 1) + aU) ^ rAx[mt]) << 4);
                LDSM_X4(a[mt][0], a[mt][1], a[mt][2], a[mt][3], ad);
            }
            uint32_t bb[4][4];
#pragma unroll
            for (int np = 0; np < 4; np++) {
                uint32_t bd = bBase + rB128[np] + ((((ks << 1) + bU) ^ rBx[np]) << 4);
                LDSM_X4(bb[np][0], bb[np][1], bb[np][2], bb[np][3], bd);
            }
#pragma unroll
            for (int mt = 0; mt < 4; mt++)
#pragma unroll
                for (int np = 0; np < 4; np++) {
                    MMA16816(c[mt][2 * np][0], c[mt][2 * np][1], c[mt][2 * np][2], c[mt][2 * np][3],
                             a[mt][0], a[mt][1], a[mt][2], a[mt][3], bb[np][0], bb[np][1]);
                    MMA16816(c[mt][2 * np + 1][0], c[mt][2 * np + 1][1], c[mt][2 * np + 1][2], c[mt][2 * np + 1][3],
                             a[mt][0], a[mt][1], a[mt][2], a[mt][3], bb[np][2], bb[np][3]);
                }
        }

        if (kt == 47) {
            // fused epilogue: acc += v[n] * tanh(c + dec_p[n])
            const int nb = cch * 256 + wn * 64 + (lane & 3) * 2;
#pragma unroll
            for (int mt = 0; mt < 4; mt++)
#pragma unroll
                for (int nt = 0; nt < 8; nt++) {
                    int n = nb + nt * 8;
                    float2 d0 = vdp[n], d1 = vdp[n + 1];
                    accA[mt] += d0.y * fast_tanh(c[mt][nt][0] + d0.x)
                              + d1.y * fast_tanh(c[mt][nt][1] + d1.x);
                    accB[mt] += d0.y * fast_tanh(c[mt][nt][2] + d0.x)
                              + d1.y * fast_tanh(c[mt][nt][3] + d1.x);
                }
            cch++;
            kt = 0;
        } else {
            kt++;
        }
    }

    // reduce across the 4 n-lanes of each quad, then across warps via smem
#pragma unroll
    for (int mt = 0; mt < 4; mt++) {
        accA[mt] += __shfl_xor_sync(0xffffffffu, accA[mt], 1);
        accA[mt] += __shfl_xor_sync(0xffffffffu, accA[mt], 2);
        accB[mt] += __shfl_xor_sync(0xffffffffu, accB[mt], 1);
        accB[mt] += __shfl_xor_sync(0xffffffffu, accB[mt], 2);
        if ((lane & 3) == 0) {
            int r = wm * 64 + mt * 16 + (lane >> 2);
            atomicAdd(&srow[r], accA[mt]);
            atomicAdd(&srow[r + 8], accB[mt]);
        }
    }
    __syncthreads();
    if (tid < 128) g_scores[m0 + tid] = srow[tid];
}

// ---------------------------------------------------------------------------
// masked softmax over T, one block per batch row
// ---------------------------------------------------------------------------
__global__ void softmax_kernel(const int* __restrict__ mask,
                               float* __restrict__ attn) {
    const int b = blockIdx.x;
    const int tid = threadIdx.x;
    __shared__ float red[8];

    float vals[8];
    float mx = -INFINITY;
#pragma unroll
    for (int i = 0; i < 8; i++) {
        int t = tid + i * 256;
        float sc = g_scores[b * T + t];
        if (mask[b * T + t] == 0) sc = NEGV;
        vals[i] = sc;
        mx = fmaxf(mx, sc);
    }
#pragma unroll
    for (int off = 16; off; off >>= 1)
        mx = fmaxf(mx, __shfl_xor_sync(0xffffffffu, mx, off));
    if ((tid & 31) == 0) red[tid >> 5] = mx;
    __syncthreads();
    if (tid < 32) {
        float m = (tid < 8) ? red[tid] : -INFINITY;
#pragma unroll
        for (int off = 4; off; off >>= 1)
            m = fmaxf(m, __shfl_xor_sync(0xffffffffu, m, off));
        if (tid == 0) red[0] = m;
    }
    __syncthreads();
    mx = red[0];

    float sum = 0.f;
#pragma unroll
    for (int i = 0; i < 8; i++) {
        vals[i] = expf(vals[i] - mx);
        sum += vals[i];
    }
#pragma unroll
    for (int off = 16; off; off >>= 1)
        sum += __shfl_xor_sync(0xffffffffu, sum, off);
    __syncthreads();
    if ((tid & 31) == 0) red[tid >> 5] = sum;
    __syncthreads();
    if (tid < 32) {
        float s = (tid < 8) ? red[tid] : 0.f;
#pragma unroll
        for (int off = 4; off; off >>= 1)
            s += __shfl_xor_sync(0xffffffffu, s, off);
        if (tid == 0) red[0] = s;
    }
    __syncthreads();
    const float inv = 1.f / red[0];
#pragma unroll
    for (int i = 0; i < 8; i++)
        attn[b * T + tid + i * 256] = vals[i] * inv;
}

// ---------------------------------------------------------------------------
// context[b,h] = sum_t attn[b,t]*enc[b,t,h]
// ---------------------------------------------------------------------------
#define TSPLIT 4
__global__ void context_kernel(const float* __restrict__ enc,
                               const float* __restrict__ attn,
                               float* __restrict__ ctx) {
    __shared__ float w[T / TSPLIT];
    const int b = blockIdx.y;
    const int t0 = blockIdx.z * (T / TSPLIT);
    const int tid = threadIdx.x;
    for (int t = tid; t < T / TSPLIT; t += 256) w[t] = attn[b * T + t0 + t];
    __syncthreads();

    const int h = blockIdx.x * 256 + tid;
    const float* e = enc + (size_t)b * T * H + (size_t)t0 * H + h;
    float a0 = 0.f, a1 = 0.f, a2 = 0.f, a3 = 0.f;
#pragma unroll 4
    for (int t = 0; t < T / TSPLIT; t += 4) {
        a0 += w[t + 0] * e[(size_t)(t + 0) * H];
        a1 += w[t + 1] * e[(size_t)(t + 1) * H];
        a2 += w[t + 2] * e[(size_t)(t + 2) * H];
        a3 += w[t + 3] * e[(size_t)(t + 3) * H];
    }
    atomicAdd(&ctx[b * H + h], (a0 + a1) + (a2 + a3));
}

// ---------------------------------------------------------------------------
extern "C" void kernel_launch(void* const* d_in, const int* in_sizes, int n_in,
                              void* d_out, int out_size) {
    const float* dec  = (const float*)d_in[0];  // [B,H]
    const float* enc  = (const float*)d_in[1];  // [B,T,H]
    const int*   mask = (const int*)d_in[2];    // [B,T]
    const float* We   = (const float*)d_in[3];  // [H,H]
    const float* Wd   = (const float*)d_in[4];  // [H,H]
    const float* v    = (const float*)d_in[5];  // [H]

    float* ctx  = (float*)d_out;                // [B,H]
    float* attn = (float*)d_out + B * H;        // [B,T]

    cudaFuncSetAttribute(scores_tc_kernel,
                         cudaFuncAttributeMaxDynamicSharedMemorySize, SMEM_TOTAL);

    split_enc_kernel<<<(B * T * H / 4 + 255) / 256, 256>>>(enc);
    split_We_kernel<<<(H * H / 4 + 255) / 256, 256>>>(We);
    dec_proj_kernel<<<(B * H * 32 + 255) / 256, 256>>>(dec, Wd);
    cudaMemsetAsync(ctx, 0, (size_t)B * H * sizeof(float));

    scores_tc_kernel<<<(B * T) / 128, 256, SMEM_TOTAL>>>(v);

    softmax_kernel<<<B, 256>>>(mask, attn);
    context_kernel<<<dim3(H / 256, B, TSPLIT), 256>>>(enc, attn, ctx);
}